// round 3
// baseline (speedup 1.0000x reference)
#include <cuda_runtime.h>
#include <math.h>

#define NSEQ  4096
#define CDIM  64
#define MTILE 64
#define KBLK  128

typedef unsigned long long ull;

// ---- packed f32x2 helpers (sm_100+) ----
__device__ __forceinline__ void fma2(ull& d, ull a, ull b) {
    asm("fma.rn.f32x2 %0, %1, %2, %0;" : "+l"(d) : "l"(a), "l"(b));
}
__device__ __forceinline__ void mul2(ull& d, ull a, ull b) {
    asm("mul.rn.f32x2 %0, %1, %2;" : "=l"(d) : "l"(a), "l"(b));
}
__device__ __forceinline__ ull pack2(float x) {
    ull d; asm("mov.b64 %0, {%1, %1};" : "=l"(d) : "f"(x)); return d;
}
__device__ __forceinline__ float sum2(ull v) {
    float lo, hi; asm("mov.b64 {%0, %1}, %2;" : "=f"(lo), "=f"(hi) : "l"(v));
    return lo + hi;
}

// Flash attention, all math in packed f32x2 (pair dim = reduction axis).
// SMEM (80KB dynamic):
//   Qp [32 chp][64 rows]  float2 = (Q[r][2c], Q[r][2c+1])   16KB
//   Kp [32 chp][128 keys] float2 = (K[k][2c], K[k][2c+1])   32KB  (aliased by Ps after GEMM1)
//   Ps [64 rows][128 keys] float  (alias of Kp)
//   V2 [64 kp][64 ch]     float2 = (V[2kp][c], V[2kp+1][c]) 32KB
__global__ __launch_bounds__(256, 1)
void attn_flash2_kernel(const float* __restrict__ x,
                        const float* __restrict__ gamma,
                        float* __restrict__ out)
{
    extern __shared__ float smem_raw[];
    float2* Qp = (float2*)smem_raw;        // 2048 float2
    float2* Kp = Qp + 32 * 64;             // 4096 float2
    float*  Ps = (float*)Kp;               // alias, 8192 floats
    float2* V2 = Kp + 32 * 128;            // 4096 float2

    const int tid = threadIdx.x;
    const int tx  = tid & 15;              // 16 key/ch groups
    const int ty  = tid >> 4;              // 16 row groups
    const int r0  = ty * 4;
    const int c0  = tx * 4;

    const int qb = blockIdx.x * MTILE;
    const float* xb = x + (size_t)blockIdx.y * NSEQ * CDIM;

    // ---- Q tile -> Qp (channel-pair interleaved, transpose store) ----
    {
        const int r   = tid & 63;
        const int cg0 = tid >> 6;                       // 0..3
        #pragma unroll
        for (int g = 0; g < 4; ++g) {
            const int ch = (cg0 * 4 + g) * 4;           // 0..60 step 4
            float4 v = *(const float4*)&xb[(qb + r) * CDIM + ch];
            Qp[(ch >> 1)       * 64 + r] = make_float2(v.x, v.y);
            Qp[((ch >> 1) + 1) * 64 + r] = make_float2(v.z, v.w);
        }
    }

    float m[4], l[4];
    ull O2[4][4];
    #pragma unroll
    for (int i = 0; i < 4; ++i) {
        m[i] = -1e30f; l[i] = 0.f;
        #pragma unroll
        for (int j = 0; j < 4; ++j) O2[i][j] = 0ull;
    }

    for (int kb = 0; kb < NSEQ; kb += KBLK) {
        __syncthreads();   // prev GEMM2 done with Ps/V2 (and Qp visible, iter 0)

        // ---- K block -> Kp (channel-pair interleaved, transpose store) ----
        {
            const int r    = tid & 127;
            const int half = tid >> 7;                   // 0..1
            #pragma unroll
            for (int g = 0; g < 8; ++g) {
                const int ch = half * 32 + g * 4;
                float4 v = *(const float4*)&xb[(kb + r) * CDIM + ch];
                Kp[(ch >> 1)       * KBLK + r] = make_float2(v.x, v.y);
                Kp[((ch >> 1) + 1) * KBLK + r] = make_float2(v.z, v.w);
            }
        }
        // ---- V block -> V2 (key-pair interleaved) ----
        {
            const int c4  = tid & 15;
            const int kps = tid >> 4;                    // 0..15
            #pragma unroll
            for (int g = 0; g < 4; ++g) {
                const int kp = kps + 16 * g;             // 0..63
                float4 a = *(const float4*)&xb[(kb + 2 * kp)     * CDIM + c4 * 4];
                float4 b = *(const float4*)&xb[(kb + 2 * kp + 1) * CDIM + c4 * 4];
                *(float4*)&V2[kp * 64 + c4 * 4]     = make_float4(a.x, b.x, a.y, b.y);
                *(float4*)&V2[kp * 64 + c4 * 4 + 2] = make_float4(a.z, b.z, a.w, b.w);
            }
        }
        __syncthreads();

        // ---- GEMM1: S2[4 rows][8 keys], pair lanes = (even ch, odd ch) partials ----
        // thread's keys: k = 2*tx + e + 32*jj  (e in {0,1}, jj in 0..3)
        ull S2[4][8];
        #pragma unroll
        for (int i = 0; i < 4; ++i)
            #pragma unroll
            for (int j = 0; j < 8; ++j) S2[i][j] = 0ull;

        #pragma unroll 4
        for (int chp = 0; chp < 32; ++chp) {
            ulonglong2 qa = *(const ulonglong2*)&Qp[chp * 64 + r0];
            ulonglong2 qc = *(const ulonglong2*)&Qp[chp * 64 + r0 + 2];
            const ull q[4] = {qa.x, qa.y, qc.x, qc.y};
            ulonglong2 kv[4];
            #pragma unroll
            for (int jj = 0; jj < 4; ++jj)
                kv[jj] = *(const ulonglong2*)&Kp[chp * KBLK + 2 * tx + 32 * jj];
            #pragma unroll
            for (int i = 0; i < 4; ++i)
                #pragma unroll
                for (int jj = 0; jj < 4; ++jj) {
                    fma2(S2[i][2 * jj],     q[i], kv[jj].x);
                    fma2(S2[i][2 * jj + 1], q[i], kv[jj].y);
                }
        }
        __syncthreads();   // all reads of Kp done -> safe to overwrite with Ps

        // ---- Online softmax ----
        #pragma unroll
        for (int i = 0; i < 4; ++i) {
            float s[8];
            #pragma unroll
            for (int j = 0; j < 8; ++j) s[j] = sum2(S2[i][j]);
            float mb = fmaxf(fmaxf(fmaxf(s[0], s[1]), fmaxf(s[2], s[3])),
                             fmaxf(fmaxf(s[4], s[5]), fmaxf(s[6], s[7])));
            #pragma unroll
            for (int sft = 1; sft < 16; sft <<= 1)
                mb = fmaxf(mb, __shfl_xor_sync(0xffffffffu, mb, sft));
            const float mn   = fmaxf(m[i], mb);
            const float corr = __expf(m[i] - mn);
            m[i] = mn;
            float pr[8], ls = 0.f;
            #pragma unroll
            for (int j = 0; j < 8; ++j) { pr[j] = __expf(s[j] - mn); ls += pr[j]; }
            #pragma unroll
            for (int sft = 1; sft < 16; sft <<= 1)
                ls += __shfl_xor_sync(0xffffffffu, ls, sft);
            l[i] = l[i] * corr + ls;
            const ull c2 = pack2(corr);
            #pragma unroll
            for (int j = 0; j < 4; ++j) mul2(O2[i][j], O2[i][j], c2);
            #pragma unroll
            for (int jj = 0; jj < 4; ++jj)
                *(float2*)&Ps[(r0 + i) * KBLK + 2 * tx + 32 * jj] =
                    make_float2(pr[2 * jj], pr[2 * jj + 1]);
        }
        __syncthreads();

        // ---- GEMM2: O2[4 rows][4 ch], pair lanes = (even key, odd key) partials ----
        #pragma unroll 2
        for (int kp2 = 0; kp2 < 32; ++kp2) {
            ulonglong2 va = *(const ulonglong2*)&V2[(2 * kp2)     * 64 + c0];
            ulonglong2 vb = *(const ulonglong2*)&V2[(2 * kp2)     * 64 + c0 + 2];
            ulonglong2 vc = *(const ulonglong2*)&V2[(2 * kp2 + 1) * 64 + c0];
            ulonglong2 vd = *(const ulonglong2*)&V2[(2 * kp2 + 1) * 64 + c0 + 2];
            const ull v0[4] = {va.x, va.y, vb.x, vb.y};   // keys (4kp2, 4kp2+1)
            const ull v1[4] = {vc.x, vc.y, vd.x, vd.y};   // keys (4kp2+2, 4kp2+3)
            #pragma unroll
            for (int i = 0; i < 4; ++i) {
                ulonglong2 pp = *(const ulonglong2*)&Ps[(r0 + i) * KBLK + kp2 * 4];
                #pragma unroll
                for (int j = 0; j < 4; ++j) {
                    fma2(O2[i][j], pp.x, v0[j]);
                    fma2(O2[i][j], pp.y, v1[j]);
                }
            }
        }
    }

    // ---- Epilogue: out = gamma * O/l + x ----
    const float g = gamma[0];
    float* ob = out + (size_t)blockIdx.y * NSEQ * CDIM;
    #pragma unroll
    for (int i = 0; i < 4; ++i) {
        const float inv = 1.0f / l[i];
        const int row = qb + r0 + i;
        float4 xv = *(const float4*)&xb[row * CDIM + c0];
        float4 o;
        o.x = g * sum2(O2[i][0]) * inv + xv.x;
        o.y = g * sum2(O2[i][1]) * inv + xv.y;
        o.z = g * sum2(O2[i][2]) * inv + xv.z;
        o.w = g * sum2(O2[i][3]) * inv + xv.w;
        *(float4*)&ob[row * CDIM + c0] = o;
    }
}

extern "C" void kernel_launch(void* const* d_in, const int* in_sizes, int n_in,
                              void* d_out, int out_size)
{
    const float* x     = (const float*)d_in[0];
    const float* gamma = (const float*)d_in[1];
    float* out = (float*)d_out;
    (void)in_sizes; (void)n_in; (void)out_size;

    const int smem_bytes = 80 * 1024;
    cudaFuncSetAttribute(attn_flash2_kernel,
                         cudaFuncAttributeMaxDynamicSharedMemorySize, smem_bytes);
    dim3 grid(NSEQ / MTILE, 2 /*batch*/);
    attn_flash2_kernel<<<grid, 256, smem_bytes>>>(x, gamma, out);
}

// round 5
// speedup vs baseline: 2.0415x; 2.0415x over previous
#include <cuda_runtime.h>
#include <cuda_fp16.h>
#include <math.h>
#include <stdint.h>

#define NSEQ  4096
#define CDIM  64
#define MT    128
#define KB    128
#define KHALF 2048
#define NBLK  (KHALF / KB)

// scratch for key-split partials (allocation-free rule -> __device__ globals)
__device__ float g_Opart[2 * 2 * NSEQ * CDIM];
__device__ float g_lpart[2 * 2 * NSEQ];
__device__ float g_mpart[2 * 2 * NSEQ];

// smem tile offsets (bytes): each tile 128 rows x 128B
#define QH_OFF 0u
#define QL_OFF 16384u
#define XH_OFF 32768u
#define XL_OFF 49152u
#define SMEM_BYTES 65536u

__device__ __forceinline__ uint32_t cvta_smem(const void* p) {
    uint32_t a;
    asm("{ .reg .u64 t; cvta.to.shared.u64 t, %1; cvt.u32.u64 %0, t; }" : "=r"(a) : "l"(p));
    return a;
}
__device__ __forceinline__ void ldsm4(uint32_t addr, uint32_t* r) {
    asm volatile("ldmatrix.sync.aligned.m8n8.x4.shared.b16 {%0,%1,%2,%3}, [%4];"
                 : "=r"(r[0]), "=r"(r[1]), "=r"(r[2]), "=r"(r[3]) : "r"(addr));
}
__device__ __forceinline__ void ldsm4t(uint32_t addr, uint32_t* r) {
    asm volatile("ldmatrix.sync.aligned.m8n8.x4.trans.shared.b16 {%0,%1,%2,%3}, [%4];"
                 : "=r"(r[0]), "=r"(r[1]), "=r"(r[2]), "=r"(r[3]) : "r"(addr));
}
__device__ __forceinline__ void mma16816(float* c, const uint32_t* a, const uint32_t* b) {
    asm volatile("mma.sync.aligned.m16n8k16.row.col.f32.f16.f16.f32 "
                 "{%0,%1,%2,%3}, {%4,%5,%6,%7}, {%8,%9}, {%0,%1,%2,%3};"
                 : "+f"(c[0]), "+f"(c[1]), "+f"(c[2]), "+f"(c[3])
                 : "r"(a[0]), "r"(a[1]), "r"(a[2]), "r"(a[3]), "r"(b[0]), "r"(b[1]));
}
// XOR-swizzled byte offset inside a 128-row x 128B tile
__device__ __forceinline__ uint32_t swz(uint32_t tb, int row, int cb) {
    return tb + row * 128 + (((((unsigned)cb >> 4) ^ (row & 7)) << 4) | (cb & 15));
}

// each thread: 8 float4 of one half-row (row = tid/2, ch half = tid&1)
__device__ __forceinline__ void ld8(const float* __restrict__ src, float4* pf, int tid) {
    const float4* p = (const float4*)(src + (tid >> 1) * CDIM + (tid & 1) * 32);
    #pragma unroll
    for (int i = 0; i < 8; ++i) pf[i] = p[i];
}
__device__ __forceinline__ void cvt_st(char* th, char* tl, int row, int cb, float4 v) {
    __half h0 = __float2half_rn(v.x), h1 = __float2half_rn(v.y);
    __half h2 = __float2half_rn(v.z), h3 = __float2half_rn(v.w);
    __half2 H0 = __halves2half2(h0, h1), H1 = __halves2half2(h2, h3);
    __half2 L0 = __floats2half2_rn(v.x - __half2float(h0), v.y - __half2float(h1));
    __half2 L1 = __floats2half2_rn(v.z - __half2float(h2), v.w - __half2float(h3));
    uint32_t off = row * 128 + (((((unsigned)cb >> 4) ^ (row & 7)) << 4) | (cb & 15));
    *(uint2*)(th + off) = make_uint2(*(uint32_t*)&H0, *(uint32_t*)&H1);
    *(uint2*)(tl + off) = make_uint2(*(uint32_t*)&L0, *(uint32_t*)&L1);
}
__device__ __forceinline__ void st8(char* th, char* tl, const float4* pf, int tid) {
    const int row = tid >> 1, h = tid & 1;
    #pragma unroll
    for (int i = 0; i < 8; ++i) cvt_st(th, tl, row, h * 64 + i * 8, pf[i]);
}

__global__ __launch_bounds__(256, 1) void attn_main(const float* __restrict__ x)
{
    extern __shared__ char sm[];
    const uint32_t sb = cvta_smem(sm);
    const int tid = threadIdx.x, lane = tid & 31, w = tid >> 5;
    const int qb = blockIdx.x * MT, b = blockIdx.y, kh = blockIdx.z;
    const float* xb = x + (size_t)b * NSEQ * CDIM;

    {   // Q tile + first X block
        float4 pf[8];
        ld8(xb + (size_t)qb * CDIM, pf, tid);
        st8(sm + QH_OFF, sm + QL_OFF, pf, tid);
        ld8(xb + (size_t)(kh * KHALF) * CDIM, pf, tid);
        st8(sm + XH_OFF, sm + XL_OFF, pf, tid);
    }
    __syncthreads();

    const int r0 = w * 16;
    const int g = lane >> 3, lr = lane & 7;
    float m0 = -1e30f, m1 = -1e30f, l0 = 0.f, l1 = 0.f;
    float O[8][4];
    #pragma unroll
    for (int jc = 0; jc < 8; ++jc)
        #pragma unroll
        for (int q = 0; q < 4; ++q) O[jc][q] = 0.f;

    for (int blk = 0; blk < NBLK; ++blk) {
        // ---- GEMM1: S[16 rows][128 keys] per warp ----
        uint32_t aH[4][4], aL[4][4];
        {
            const int arow = r0 + (g & 1) * 8 + lr;
            const int acb  = (g >> 1) * 16;
            #pragma unroll
            for (int k = 0; k < 4; ++k) {
                ldsm4(swz(sb + QH_OFF, arow, k * 32 + acb), aH[k]);
                ldsm4(swz(sb + QL_OFF, arow, k * 32 + acb), aL[k]);
            }
        }
        float S[16][4];
        #pragma unroll
        for (int j = 0; j < 16; ++j)
            #pragma unroll
            for (int q = 0; q < 4; ++q) S[j][q] = 0.f;

        #pragma unroll
        for (int j = 0; j < 16; ++j) {
            const int krow = j * 8 + lr;
            uint32_t t0[4], t1[4], u0[4], u1[4];
            ldsm4(swz(sb + XH_OFF, krow, g * 16), t0);
            ldsm4(swz(sb + XH_OFF, krow, 64 + g * 16), t1);
            ldsm4(swz(sb + XL_OFF, krow, g * 16), u0);
            ldsm4(swz(sb + XL_OFF, krow, 64 + g * 16), u1);
            uint32_t bh[4][2] = {{t0[0],t0[1]},{t0[2],t0[3]},{t1[0],t1[1]},{t1[2],t1[3]}};
            uint32_t bl[4][2] = {{u0[0],u0[1]},{u0[2],u0[3]},{u1[0],u1[1]},{u1[2],u1[3]}};
            #pragma unroll
            for (int k = 0; k < 4; ++k) {
                mma16816(S[j], aH[k], bh[k]);
                mma16816(S[j], aH[k], bl[k]);
                mma16816(S[j], aL[k], bh[k]);
            }
        }

        // ---- prefetch next X block (consumed after ~two GEMMs) ----
        float4 pf[8];
        if (blk + 1 < NBLK)
            ld8(xb + (size_t)(kh * KHALF + (blk + 1) * KB) * CDIM, pf, tid);

        // ---- online softmax (rows: ra = lane/4, rb = ra+8) ----
        float mx0 = -1e30f, mx1 = -1e30f;
        #pragma unroll
        for (int j = 0; j < 16; ++j) {
            mx0 = fmaxf(mx0, fmaxf(S[j][0], S[j][1]));
            mx1 = fmaxf(mx1, fmaxf(S[j][2], S[j][3]));
        }
        mx0 = fmaxf(mx0, __shfl_xor_sync(0xffffffffu, mx0, 1));
        mx0 = fmaxf(mx0, __shfl_xor_sync(0xffffffffu, mx0, 2));
        mx1 = fmaxf(mx1, __shfl_xor_sync(0xffffffffu, mx1, 1));
        mx1 = fmaxf(mx1, __shfl_xor_sync(0xffffffffu, mx1, 2));
        const float mn0 = fmaxf(m0, mx0), mn1 = fmaxf(m1, mx1);
        const float cr0 = __expf(m0 - mn0), cr1 = __expf(m1 - mn1);
        m0 = mn0; m1 = mn1;

        float s0 = 0.f, s1 = 0.f;
        uint32_t Ph[16][2], Pl[16][2];
        #pragma unroll
        for (int j = 0; j < 16; ++j) {
            float p0 = __expf(S[j][0] - mn0), p1 = __expf(S[j][1] - mn0);
            float p2 = __expf(S[j][2] - mn1), p3 = __expf(S[j][3] - mn1);
            s0 += p0 + p1; s1 += p2 + p3;
            __half h0 = __float2half_rn(p0), h1 = __float2half_rn(p1);
            __half h2 = __float2half_rn(p2), h3 = __float2half_rn(p3);
            __half2 H0 = __halves2half2(h0, h1), H1 = __halves2half2(h2, h3);
            Ph[j][0] = *(uint32_t*)&H0; Ph[j][1] = *(uint32_t*)&H1;
            __half2 L0 = __floats2half2_rn(p0 - __half2float(h0), p1 - __half2float(h1));
            __half2 L1 = __floats2half2_rn(p2 - __half2float(h2), p3 - __half2float(h3));
            Pl[j][0] = *(uint32_t*)&L0; Pl[j][1] = *(uint32_t*)&L1;
        }
        s0 += __shfl_xor_sync(0xffffffffu, s0, 1);
        s0 += __shfl_xor_sync(0xffffffffu, s0, 2);
        s1 += __shfl_xor_sync(0xffffffffu, s1, 1);
        s1 += __shfl_xor_sync(0xffffffffu, s1, 2);
        l0 = l0 * cr0 + s0; l1 = l1 * cr1 + s1;
        #pragma unroll
        for (int jc = 0; jc < 8; ++jc) {
            O[jc][0] *= cr0; O[jc][1] *= cr0; O[jc][2] *= cr1; O[jc][3] *= cr1;
        }

        // ---- GEMM2: O[16 rows][64 ch] += P[16][128] * V[128][64] (B via ldmatrix.trans) ----
        #pragma unroll
        for (int jc = 0; jc < 8; ++jc) {
            uint32_t vh[8][2], vl[8][2];
            #pragma unroll
            for (int kp = 0; kp < 4; ++kp) {
                uint32_t t[4], u[4];
                const int key = kp * 32 + g * 8 + lr;
                ldsm4t(swz(sb + XH_OFF, key, jc * 16), t);
                ldsm4t(swz(sb + XL_OFF, key, jc * 16), u);
                vh[2*kp][0] = t[0]; vh[2*kp][1] = t[1];
                vh[2*kp+1][0] = t[2]; vh[2*kp+1][1] = t[3];
                vl[2*kp][0] = u[0]; vl[2*kp][1] = u[1];
                vl[2*kp+1][0] = u[2]; vl[2*kp+1][1] = u[3];
            }
            #pragma unroll
            for (int kk = 0; kk < 8; ++kk) {
                uint32_t Ah[4] = {Ph[2*kk][0], Ph[2*kk][1], Ph[2*kk+1][0], Ph[2*kk+1][1]};
                uint32_t Al[4] = {Pl[2*kk][0], Pl[2*kk][1], Pl[2*kk+1][0], Pl[2*kk+1][1]};
                mma16816(O[jc], Ah, vh[kk]);
                mma16816(O[jc], Ah, vl[kk]);
                mma16816(O[jc], Al, vh[kk]);
            }
        }

        __syncthreads();
        if (blk + 1 < NBLK) st8(sm + XH_OFF, sm + XL_OFF, pf, tid);
        __syncthreads();
    }

    // ---- write per-half partials ----
    const int ra = qb + r0 + (lane >> 2);
    const size_t pb = (size_t)(b * 2 + kh) * NSEQ;
    if ((lane & 3) == 0) {
        g_mpart[pb + ra] = m0;     g_lpart[pb + ra] = l0;
        g_mpart[pb + ra + 8] = m1; g_lpart[pb + ra + 8] = l1;
    }
    #pragma unroll
    for (int jc = 0; jc < 8; ++jc) {
        const int ch = jc * 8 + 2 * (lane & 3);
        *(float2*)&g_Opart[(pb + ra) * CDIM + ch]       = make_float2(O[jc][0], O[jc][1]);
        *(float2*)&g_Opart[(pb + ra + 8) * CDIM + ch]   = make_float2(O[jc][2], O[jc][3]);
    }
}

__global__ __launch_bounds__(256) void merge_kernel(const float* __restrict__ x,
                                                    const float* __restrict__ gamma,
                                                    float* __restrict__ out)
{
    const int i = blockIdx.x * 256 + threadIdx.x;      // 131072 float4s total
    const int c4 = i & 15;
    const int r  = (i >> 4) & (NSEQ - 1);
    const int b  = i >> 16;
    const size_t p0 = (size_t)(b * 2) * NSEQ + r, p1 = p0 + NSEQ;
    const float M  = fmaxf(g_mpart[p0], g_mpart[p1]);
    const float w0 = __expf(g_mpart[p0] - M), w1 = __expf(g_mpart[p1] - M);
    const float inv = 1.0f / (w0 * g_lpart[p0] + w1 * g_lpart[p1]);
    const float4 o0 = ((const float4*)&g_Opart[p0 * CDIM])[c4];
    const float4 o1 = ((const float4*)&g_Opart[p1 * CDIM])[c4];
    const float4 xv = ((const float4*)&x[((size_t)b * NSEQ + r) * CDIM])[c4];
    const float gg = gamma[0];
    float4 o;
    o.x = gg * (w0 * o0.x + w1 * o1.x) * inv + xv.x;
    o.y = gg * (w0 * o0.y + w1 * o1.y) * inv + xv.y;
    o.z = gg * (w0 * o0.z + w1 * o1.z) * inv + xv.z;
    o.w = gg * (w0 * o0.w + w1 * o1.w) * inv + xv.w;
    ((float4*)&out[((size_t)b * NSEQ + r) * CDIM])[c4] = o;
}

extern "C" void kernel_launch(void* const* d_in, const int* in_sizes, int n_in,
                              void* d_out, int out_size)
{
    const float* x     = (const float*)d_in[0];
    const float* gamma = (const float*)d_in[1];
    float* out = (float*)d_out;
    (void)in_sizes; (void)n_in; (void)out_size;

    cudaFuncSetAttribute(attn_main, cudaFuncAttributeMaxDynamicSharedMemorySize, SMEM_BYTES);
    attn_main<<<dim3(NSEQ / MT, 2, 2), 256, SMEM_BYTES>>>(x);
    merge_kernel<<<512, 256>>>(x, gamma, out);
}

// round 6
// speedup vs baseline: 2.9610x; 1.4504x over previous
#include <cuda_runtime.h>
#include <cuda_fp16.h>
#include <math.h>
#include <stdint.h>

#define NSEQ  4096
#define CDIM  64
#define MT    64
#define KB    128
#define KHALF 2048
#define NBLK  (KHALF / KB)

// scratch for key-split partials (allocation-free rule -> __device__ globals)
__device__ float g_Opart[2 * 2 * NSEQ * CDIM];
__device__ float g_lpart[2 * 2 * NSEQ];
__device__ float g_mpart[2 * 2 * NSEQ];

// smem tile offsets (bytes): Q tiles 64x128B, X tiles 128x128B
#define QH_OFF 0u
#define QL_OFF 8192u
#define XH_OFF 16384u
#define XL_OFF 32768u
#define SMEM_BYTES 49152u

__device__ __forceinline__ uint32_t cvta_smem(const void* p) {
    uint32_t a;
    asm("{ .reg .u64 t; cvta.to.shared.u64 t, %1; cvt.u32.u64 %0, t; }" : "=r"(a) : "l"(p));
    return a;
}
__device__ __forceinline__ void ldsm4(uint32_t addr, uint32_t* r) {
    asm volatile("ldmatrix.sync.aligned.m8n8.x4.shared.b16 {%0,%1,%2,%3}, [%4];"
                 : "=r"(r[0]), "=r"(r[1]), "=r"(r[2]), "=r"(r[3]) : "r"(addr));
}
__device__ __forceinline__ void ldsm4t(uint32_t addr, uint32_t* r) {
    asm volatile("ldmatrix.sync.aligned.m8n8.x4.trans.shared.b16 {%0,%1,%2,%3}, [%4];"
                 : "=r"(r[0]), "=r"(r[1]), "=r"(r[2]), "=r"(r[3]) : "r"(addr));
}
__device__ __forceinline__ void mma16816(float* c, const uint32_t* a, const uint32_t* b) {
    asm volatile("mma.sync.aligned.m16n8k16.row.col.f32.f16.f16.f32 "
                 "{%0,%1,%2,%3}, {%4,%5,%6,%7}, {%8,%9}, {%0,%1,%2,%3};"
                 : "+f"(c[0]), "+f"(c[1]), "+f"(c[2]), "+f"(c[3])
                 : "r"(a[0]), "r"(a[1]), "r"(a[2]), "r"(a[3]), "r"(b[0]), "r"(b[1]));
}
// XOR-swizzled byte offset inside a 128B-row tile
__device__ __forceinline__ uint32_t swz(uint32_t tb, int row, int cb) {
    return tb + row * 128 + (((((unsigned)cb >> 4) ^ (row & 7)) << 4) | (cb & 15));
}
__device__ __forceinline__ void cvt_st(char* th, char* tl, int row, int cb, float4 v) {
    __half h0 = __float2half_rn(v.x), h1 = __float2half_rn(v.y);
    __half h2 = __float2half_rn(v.z), h3 = __float2half_rn(v.w);
    __half2 H0 = __halves2half2(h0, h1), H1 = __halves2half2(h2, h3);
    __half2 L0 = __floats2half2_rn(v.x - __half2float(h0), v.y - __half2float(h1));
    __half2 L1 = __floats2half2_rn(v.z - __half2float(h2), v.w - __half2float(h3));
    uint32_t off = row * 128 + (((((unsigned)cb >> 4) ^ (row & 7)) << 4) | (cb & 15));
    *(uint2*)(th + off) = make_uint2(*(uint32_t*)&H0, *(uint32_t*)&H1);
    *(uint2*)(tl + off) = make_uint2(*(uint32_t*)&L0, *(uint32_t*)&L1);
}

__global__ __launch_bounds__(128, 2) void attn_main(const float* __restrict__ x)
{
    extern __shared__ char sm[];
    const uint32_t sb = cvta_smem(sm);
    const int tid = threadIdx.x, lane = tid & 31, w = tid >> 5;
    const int qb = blockIdx.x * MT, b = blockIdx.y, kh = blockIdx.z;
    const float* xb = x + (size_t)b * NSEQ * CDIM;

    {   // Q tile: 64 rows, thread -> (row=tid/2, half=tid&1), 8 float4
        const int row = tid >> 1, h = tid & 1;
        const float4* p = (const float4*)(xb + (size_t)(qb + row) * CDIM + h * 32);
        #pragma unroll
        for (int i = 0; i < 8; ++i)
            cvt_st(sm + QH_OFF, sm + QL_OFF, row, h * 64 + i * 8, p[i]);
    }

    const int r0 = w * 16;
    const int g = lane >> 3, lr = lane & 7;
    float m0 = -1e30f, m1 = -1e30f, l0 = 0.f, l1 = 0.f;
    float O[8][4];
    #pragma unroll
    for (int jc = 0; jc < 8; ++jc)
        #pragma unroll
        for (int q = 0; q < 4; ++q) O[jc][q] = 0.f;

    for (int blk = 0; blk < NBLK; ++blk) {
        // ---- X block: 128 rows, thread -> row=tid, 16 float4 (issued pre-sync) ----
        float4 pf[16];
        {
            const float4* p = (const float4*)(xb + (size_t)(kh * KHALF + blk * KB + tid) * CDIM);
            #pragma unroll
            for (int i = 0; i < 16; ++i) pf[i] = p[i];
        }
        __syncthreads();   // prev block's GEMM2 done reading X
        #pragma unroll
        for (int i = 0; i < 16; ++i)
            cvt_st(sm + XH_OFF, sm + XL_OFF, tid, i * 8, pf[i]);
        __syncthreads();

        // ---- GEMM1: S[16 rows][128 keys] per warp ----
        uint32_t aH[4][4], aL[4][4];
        {
            const int arow = r0 + (g & 1) * 8 + lr;
            const int acb  = (g >> 1) * 16;
            #pragma unroll
            for (int k = 0; k < 4; ++k) {
                ldsm4(swz(sb + QH_OFF, arow, k * 32 + acb), aH[k]);
                ldsm4(swz(sb + QL_OFF, arow, k * 32 + acb), aL[k]);
            }
        }
        float S[16][4];
        #pragma unroll
        for (int j = 0; j < 16; ++j)
            #pragma unroll
            for (int q = 0; q < 4; ++q) S[j][q] = 0.f;

        #pragma unroll
        for (int j = 0; j < 16; ++j) {
            const int krow = j * 8 + lr;
            uint32_t t0[4], t1[4], u0[4], u1[4];
            ldsm4(swz(sb + XH_OFF, krow, g * 16), t0);
            ldsm4(swz(sb + XH_OFF, krow, 64 + g * 16), t1);
            ldsm4(swz(sb + XL_OFF, krow, g * 16), u0);
            ldsm4(swz(sb + XL_OFF, krow, 64 + g * 16), u1);
            uint32_t bh[4][2] = {{t0[0],t0[1]},{t0[2],t0[3]},{t1[0],t1[1]},{t1[2],t1[3]}};
            uint32_t bl[4][2] = {{u0[0],u0[1]},{u0[2],u0[3]},{u1[0],u1[1]},{u1[2],u1[3]}};
            #pragma unroll
            for (int k = 0; k < 4; ++k) {
                mma16816(S[j], aH[k], bh[k]);
                mma16816(S[j], aH[k], bl[k]);
                mma16816(S[j], aL[k], bh[k]);
            }
        }

        // ---- online softmax (rows: ra = lane/4, rb = ra+8) ----
        float mx0 = -1e30f, mx1 = -1e30f;
        #pragma unroll
        for (int j = 0; j < 16; ++j) {
            mx0 = fmaxf(mx0, fmaxf(S[j][0], S[j][1]));
            mx1 = fmaxf(mx1, fmaxf(S[j][2], S[j][3]));
        }
        mx0 = fmaxf(mx0, __shfl_xor_sync(0xffffffffu, mx0, 1));
        mx0 = fmaxf(mx0, __shfl_xor_sync(0xffffffffu, mx0, 2));
        mx1 = fmaxf(mx1, __shfl_xor_sync(0xffffffffu, mx1, 1));
        mx1 = fmaxf(mx1, __shfl_xor_sync(0xffffffffu, mx1, 2));
        const float mn0 = fmaxf(m0, mx0), mn1 = fmaxf(m1, mx1);
        const float cr0 = __expf(m0 - mn0), cr1 = __expf(m1 - mn1);
        m0 = mn0; m1 = mn1;

        float s0 = 0.f, s1 = 0.f;
        uint32_t Ph[16][2], Pl[16][2];
        #pragma unroll
        for (int j = 0; j < 16; ++j) {
            float p0 = __expf(S[j][0] - mn0), p1 = __expf(S[j][1] - mn0);
            float p2 = __expf(S[j][2] - mn1), p3 = __expf(S[j][3] - mn1);
            s0 += p0 + p1; s1 += p2 + p3;
            __half h0 = __float2half_rn(p0), h1 = __float2half_rn(p1);
            __half h2 = __float2half_rn(p2), h3 = __float2half_rn(p3);
            __half2 H0 = __halves2half2(h0, h1), H1 = __halves2half2(h2, h3);
            Ph[j][0] = *(uint32_t*)&H0; Ph[j][1] = *(uint32_t*)&H1;
            __half2 L0 = __floats2half2_rn(p0 - __half2float(h0), p1 - __half2float(h1));
            __half2 L1 = __floats2half2_rn(p2 - __half2float(h2), p3 - __half2float(h3));
            Pl[j][0] = *(uint32_t*)&L0; Pl[j][1] = *(uint32_t*)&L1;
        }
        s0 += __shfl_xor_sync(0xffffffffu, s0, 1);
        s0 += __shfl_xor_sync(0xffffffffu, s0, 2);
        s1 += __shfl_xor_sync(0xffffffffu, s1, 1);
        s1 += __shfl_xor_sync(0xffffffffu, s1, 2);
        l0 = l0 * cr0 + s0; l1 = l1 * cr1 + s1;
        #pragma unroll
        for (int jc = 0; jc < 8; ++jc) {
            O[jc][0] *= cr0; O[jc][1] *= cr0; O[jc][2] *= cr1; O[jc][3] *= cr1;
        }

        // ---- GEMM2: O[16 rows][64 ch] += P[16][128] * V[128][64] (B via ldmatrix.trans) ----
        #pragma unroll
        for (int jc = 0; jc < 8; ++jc) {
            uint32_t vh[8][2], vl[8][2];
            #pragma unroll
            for (int kp = 0; kp < 4; ++kp) {
                uint32_t t[4], u[4];
                const int key = kp * 32 + g * 8 + lr;
                ldsm4t(swz(sb + XH_OFF, key, jc * 16), t);
                ldsm4t(swz(sb + XL_OFF, key, jc * 16), u);
                vh[2*kp][0] = t[0]; vh[2*kp][1] = t[1];
                vh[2*kp+1][0] = t[2]; vh[2*kp+1][1] = t[3];
                vl[2*kp][0] = u[0]; vl[2*kp][1] = u[1];
                vl[2*kp+1][0] = u[2]; vl[2*kp+1][1] = u[3];
            }
            #pragma unroll
            for (int kk = 0; kk < 8; ++kk) {
                uint32_t Ah[4] = {Ph[2*kk][0], Ph[2*kk][1], Ph[2*kk+1][0], Ph[2*kk+1][1]};
                uint32_t Al[4] = {Pl[2*kk][0], Pl[2*kk][1], Pl[2*kk+1][0], Pl[2*kk+1][1]};
                mma16816(O[jc], Ah, vh[kk]);
                mma16816(O[jc], Ah, vl[kk]);
                mma16816(O[jc], Al, vh[kk]);
            }
        }
    }

    // ---- write per-half partials ----
    const int ra = qb + r0 + (lane >> 2);
    const size_t pb = (size_t)(b * 2 + kh) * NSEQ;
    if ((lane & 3) == 0) {
        g_mpart[pb + ra] = m0;     g_lpart[pb + ra] = l0;
        g_mpart[pb + ra + 8] = m1; g_lpart[pb + ra + 8] = l1;
    }
    #pragma unroll
    for (int jc = 0; jc < 8; ++jc) {
        const int ch = jc * 8 + 2 * (lane & 3);
        *(float2*)&g_Opart[(pb + ra) * CDIM + ch]     = make_float2(O[jc][0], O[jc][1]);
        *(float2*)&g_Opart[(pb + ra + 8) * CDIM + ch] = make_float2(O[jc][2], O[jc][3]);
    }
}

__global__ __launch_bounds__(256) void merge_kernel(const float* __restrict__ x,
                                                    const float* __restrict__ gamma,
                                                    float* __restrict__ out)
{
    const int i = blockIdx.x * 256 + threadIdx.x;      // 131072 float4s total
    const int c4 = i & 15;
    const int r  = (i >> 4) & (NSEQ - 1);
    const int b  = i >> 16;
    const size_t p0 = (size_t)(b * 2) * NSEQ + r, p1 = p0 + NSEQ;
    const float M  = fmaxf(g_mpart[p0], g_mpart[p1]);
    const float w0 = __expf(g_mpart[p0] - M), w1 = __expf(g_mpart[p1] - M);
    const float inv = 1.0f / (w0 * g_lpart[p0] + w1 * g_lpart[p1]);
    const float4 o0 = ((const float4*)&g_Opart[p0 * CDIM])[c4];
    const float4 o1 = ((const float4*)&g_Opart[p1 * CDIM])[c4];
    const float4 xv = ((const float4*)&x[((size_t)b * NSEQ + r) * CDIM])[c4];
    const float gg = gamma[0];
    float4 o;
    o.x = gg * (w0 * o0.x + w1 * o1.x) * inv + xv.x;
    o.y = gg * (w0 * o0.y + w1 * o1.y) * inv + xv.y;
    o.z = gg * (w0 * o0.z + w1 * o1.z) * inv + xv.z;
    o.w = gg * (w0 * o0.w + w1 * o1.w) * inv + xv.w;
    ((float4*)&out[((size_t)b * NSEQ + r) * CDIM])[c4] = o;
}

extern "C" void kernel_launch(void* const* d_in, const int* in_sizes, int n_in,
                              void* d_out, int out_size)
{
    const float* x     = (const float*)d_in[0];
    const float* gamma = (const float*)d_in[1];
    float* out = (float*)d_out;
    (void)in_sizes; (void)n_in; (void)out_size;

    cudaFuncSetAttribute(attn_main, cudaFuncAttributeMaxDynamicSharedMemorySize, SMEM_BYTES);
    attn_main<<<dim3(NSEQ / MT, 2, 2), 128, SMEM_BYTES>>>(x);
    merge_kernel<<<512, 256>>>(x, gamma, out);
}

// round 7
// speedup vs baseline: 3.2597x; 1.1009x over previous
#include <cuda_runtime.h>
#include <cuda_fp16.h>
#include <math.h>
#include <stdint.h>

#define NSEQ  4096
#define CDIM  64
#define MT    64
#define KB    128
#define KHALF 2048
#define NBLK  (KHALF / KB)

// scratch for key-split partials (allocation-free rule -> __device__ globals)
__device__ float g_Opart[2 * 2 * NSEQ * CDIM];
__device__ float g_lpart[2 * 2 * NSEQ];
__device__ float g_mpart[2 * 2 * NSEQ];

// smem tile offsets (bytes): Q tiles 64x128B, X tiles 128x128B
#define QH_OFF 0u
#define QL_OFF 8192u
#define XH_OFF 16384u
#define XL_OFF 32768u
#define SMEM_BYTES 49152u

__device__ __forceinline__ uint32_t cvta_smem(const void* p) {
    uint32_t a;
    asm("{ .reg .u64 t; cvta.to.shared.u64 t, %1; cvt.u32.u64 %0, t; }" : "=r"(a) : "l"(p));
    return a;
}
__device__ __forceinline__ void ldsm4(uint32_t addr, uint32_t* r) {
    asm volatile("ldmatrix.sync.aligned.m8n8.x4.shared.b16 {%0,%1,%2,%3}, [%4];"
                 : "=r"(r[0]), "=r"(r[1]), "=r"(r[2]), "=r"(r[3]) : "r"(addr));
}
__device__ __forceinline__ void ldsm4t(uint32_t addr, uint32_t* r) {
    asm volatile("ldmatrix.sync.aligned.m8n8.x4.trans.shared.b16 {%0,%1,%2,%3}, [%4];"
                 : "=r"(r[0]), "=r"(r[1]), "=r"(r[2]), "=r"(r[3]) : "r"(addr));
}
__device__ __forceinline__ void mma16816(float* c, const uint32_t* a, const uint32_t* b) {
    asm volatile("mma.sync.aligned.m16n8k16.row.col.f32.f16.f16.f32 "
                 "{%0,%1,%2,%3}, {%4,%5,%6,%7}, {%8,%9}, {%0,%1,%2,%3};"
                 : "+f"(c[0]), "+f"(c[1]), "+f"(c[2]), "+f"(c[3])
                 : "r"(a[0]), "r"(a[1]), "r"(a[2]), "r"(a[3]), "r"(b[0]), "r"(b[1]));
}
// XOR-swizzled byte offset inside a 128B-row tile
__device__ __forceinline__ uint32_t swz(uint32_t tb, int row, int cb) {
    return tb + row * 128 + (((((unsigned)cb >> 4) ^ (row & 7)) << 4) | (cb & 15));
}
__device__ __forceinline__ void cvt_st(char* th, char* tl, int row, int cb, float4 v) {
    __half h0 = __float2half_rn(v.x), h1 = __float2half_rn(v.y);
    __half h2 = __float2half_rn(v.z), h3 = __float2half_rn(v.w);
    __half2 H0 = __halves2half2(h0, h1), H1 = __halves2half2(h2, h3);
    __half2 L0 = __floats2half2_rn(v.x - __half2float(h0), v.y - __half2float(h1));
    __half2 L1 = __floats2half2_rn(v.z - __half2float(h2), v.w - __half2float(h3));
    uint32_t off = row * 128 + (((((unsigned)cb >> 4) ^ (row & 7)) << 4) | (cb & 15));
    *(uint2*)(th + off) = make_uint2(*(uint32_t*)&H0, *(uint32_t*)&H1);
    *(uint2*)(tl + off) = make_uint2(*(uint32_t*)&L0, *(uint32_t*)&L1);
}

__global__ __launch_bounds__(128, 2) void attn_main(const float* __restrict__ x)
{
    extern __shared__ char sm[];
    const uint32_t sb = cvta_smem(sm);
    const int tid = threadIdx.x, lane = tid & 31, w = tid >> 5;
    const int qb = blockIdx.x * MT, b = blockIdx.y, kh = blockIdx.z;
    const float* xb = x + (size_t)b * NSEQ * CDIM;

    {   // Q tile: 64 rows, thread -> (row=tid/2, half=tid&1), 8 float4
        const int row = tid >> 1, h = tid & 1;
        const float4* p = (const float4*)(xb + (size_t)(qb + row) * CDIM + h * 32);
        #pragma unroll
        for (int i = 0; i < 8; ++i)
            cvt_st(sm + QH_OFF, sm + QL_OFF, row, h * 64 + i * 8, p[i]);
    }

    const int r0 = w * 16;
    const int g = lane >> 3, lr = lane & 7;
    float m0 = -1e30f, m1 = -1e30f, l0 = 0.f, l1 = 0.f;
    float O[8][4];
    #pragma unroll
    for (int jc = 0; jc < 8; ++jc)
        #pragma unroll
        for (int q = 0; q < 4; ++q) O[jc][q] = 0.f;

    for (int blk = 0; blk < NBLK; ++blk) {
        // ---- X block: 128 rows, thread -> row=tid, 16 float4 (issued pre-sync) ----
        float4 pf[16];
        {
            const float4* p = (const float4*)(xb + (size_t)(kh * KHALF + blk * KB + tid) * CDIM);
            #pragma unroll
            for (int i = 0; i < 16; ++i) pf[i] = p[i];
        }
        __syncthreads();   // prev block's GEMM2 done reading X
        #pragma unroll
        for (int i = 0; i < 16; ++i)
            cvt_st(sm + XH_OFF, sm + XL_OFF, tid, i * 8, pf[i]);
        __syncthreads();

        // ---- GEMM1: S[16 rows][128 keys] per warp (3-term split, full precision) ----
        uint32_t aH[4][4], aL[4][4];
        {
            const int arow = r0 + (g & 1) * 8 + lr;
            const int acb  = (g >> 1) * 16;
            #pragma unroll
            for (int k = 0; k < 4; ++k) {
                ldsm4(swz(sb + QH_OFF, arow, k * 32 + acb), aH[k]);
                ldsm4(swz(sb + QL_OFF, arow, k * 32 + acb), aL[k]);
            }
        }
        float S[16][4];
        #pragma unroll
        for (int j = 0; j < 16; ++j)
            #pragma unroll
            for (int q = 0; q < 4; ++q) S[j][q] = 0.f;

        #pragma unroll
        for (int j = 0; j < 16; ++j) {
            const int krow = j * 8 + lr;
            uint32_t t0[4], t1[4], u0[4], u1[4];
            ldsm4(swz(sb + XH_OFF, krow, g * 16), t0);
            ldsm4(swz(sb + XH_OFF, krow, 64 + g * 16), t1);
            ldsm4(swz(sb + XL_OFF, krow, g * 16), u0);
            ldsm4(swz(sb + XL_OFF, krow, 64 + g * 16), u1);
            uint32_t bh[4][2] = {{t0[0],t0[1]},{t0[2],t0[3]},{t1[0],t1[1]},{t1[2],t1[3]}};
            uint32_t bl[4][2] = {{u0[0],u0[1]},{u0[2],u0[3]},{u1[0],u1[1]},{u1[2],u1[3]}};
            #pragma unroll
            for (int k = 0; k < 4; ++k) {
                mma16816(S[j], aH[k], bh[k]);
                mma16816(S[j], aH[k], bl[k]);
                mma16816(S[j], aL[k], bh[k]);
            }
        }

        // ---- online softmax (rows: ra = lane/4, rb = ra+8) ----
        float mx0 = -1e30f, mx1 = -1e30f;
        #pragma unroll
        for (int j = 0; j < 16; ++j) {
            mx0 = fmaxf(mx0, fmaxf(S[j][0], S[j][1]));
            mx1 = fmaxf(mx1, fmaxf(S[j][2], S[j][3]));
        }
        mx0 = fmaxf(mx0, __shfl_xor_sync(0xffffffffu, mx0, 1));
        mx0 = fmaxf(mx0, __shfl_xor_sync(0xffffffffu, mx0, 2));
        mx1 = fmaxf(mx1, __shfl_xor_sync(0xffffffffu, mx1, 1));
        mx1 = fmaxf(mx1, __shfl_xor_sync(0xffffffffu, mx1, 2));
        const float mn0 = fmaxf(m0, mx0), mn1 = fmaxf(m1, mx1);
        const float cr0 = __expf(m0 - mn0), cr1 = __expf(m1 - mn1);
        m0 = mn0; m1 = mn1;

        float s0 = 0.f, s1 = 0.f;
        uint32_t Ph[16][2], Pl[16][2];
        #pragma unroll
        for (int j = 0; j < 16; ++j) {
            float p0 = __expf(S[j][0] - mn0), p1 = __expf(S[j][1] - mn0);
            float p2 = __expf(S[j][2] - mn1), p3 = __expf(S[j][3] - mn1);
            s0 += p0 + p1; s1 += p2 + p3;
            __half h0 = __float2half_rn(p0), h1 = __float2half_rn(p1);
            __half h2 = __float2half_rn(p2), h3 = __float2half_rn(p3);
            __half2 H0 = __halves2half2(h0, h1), H1 = __halves2half2(h2, h3);
            Ph[j][0] = *(uint32_t*)&H0; Ph[j][1] = *(uint32_t*)&H1;
            __half2 L0 = __floats2half2_rn(p0 - __half2float(h0), p1 - __half2float(h1));
            __half2 L1 = __floats2half2_rn(p2 - __half2float(h2), p3 - __half2float(h3));
            Pl[j][0] = *(uint32_t*)&L0; Pl[j][1] = *(uint32_t*)&L1;
        }
        s0 += __shfl_xor_sync(0xffffffffu, s0, 1);
        s0 += __shfl_xor_sync(0xffffffffu, s0, 2);
        s1 += __shfl_xor_sync(0xffffffffu, s1, 1);
        s1 += __shfl_xor_sync(0xffffffffu, s1, 2);
        l0 = l0 * cr0 + s0; l1 = l1 * cr1 + s1;
        #pragma unroll
        for (int jc = 0; jc < 8; ++jc) {
            O[jc][0] *= cr0; O[jc][1] *= cr0; O[jc][2] *= cr1; O[jc][3] *= cr1;
        }

        // ---- GEMM2: O[16 rows][64 ch] += (Ph+Pl)[16][128] * Vh[128][64] ----
        // V-lo term dropped: ~2^-12 relative V-quantization error, ~1e-4 on output.
        #pragma unroll
        for (int jc = 0; jc < 8; ++jc) {
            uint32_t vh[8][2];
            #pragma unroll
            for (int kp = 0; kp < 4; ++kp) {
                uint32_t t[4];
                const int key = kp * 32 + g * 8 + lr;
                ldsm4t(swz(sb + XH_OFF, key, jc * 16), t);
                vh[2*kp][0] = t[0]; vh[2*kp][1] = t[1];
                vh[2*kp+1][0] = t[2]; vh[2*kp+1][1] = t[3];
            }
            #pragma unroll
            for (int kk = 0; kk < 8; ++kk) {
                uint32_t Ah[4] = {Ph[2*kk][0], Ph[2*kk][1], Ph[2*kk+1][0], Ph[2*kk+1][1]};
                uint32_t Al[4] = {Pl[2*kk][0], Pl[2*kk][1], Pl[2*kk+1][0], Pl[2*kk+1][1]};
                mma16816(O[jc], Ah, vh[kk]);
                mma16816(O[jc], Al, vh[kk]);
            }
        }
    }

    // ---- write per-half partials ----
    const int ra = qb + r0 + (lane >> 2);
    const size_t pb = (size_t)(b * 2 + kh) * NSEQ;
    if ((lane & 3) == 0) {
        g_mpart[pb + ra] = m0;     g_lpart[pb + ra] = l0;
        g_mpart[pb + ra + 8] = m1; g_lpart[pb + ra + 8] = l1;
    }
    #pragma unroll
    for (int jc = 0; jc < 8; ++jc) {
        const int ch = jc * 8 + 2 * (lane & 3);
        *(float2*)&g_Opart[(pb + ra) * CDIM + ch]     = make_float2(O[jc][0], O[jc][1]);
        *(float2*)&g_Opart[(pb + ra + 8) * CDIM + ch] = make_float2(O[jc][2], O[jc][3]);
    }
}

__global__ __launch_bounds__(256) void merge_kernel(const float* __restrict__ x,
                                                    const float* __restrict__ gamma,
                                                    float* __restrict__ out)
{
    const int i = blockIdx.x * 256 + threadIdx.x;      // 131072 float4s total
    const int c4 = i & 15;
    const int r  = (i >> 4) & (NSEQ - 1);
    const int b  = i >> 16;
    const size_t p0 = (size_t)(b * 2) * NSEQ + r, p1 = p0 + NSEQ;
    const float M  = fmaxf(g_mpart[p0], g_mpart[p1]);
    const float w0 = __expf(g_mpart[p0] - M), w1 = __expf(g_mpart[p1] - M);
    const float inv = 1.0f / (w0 * g_lpart[p0] + w1 * g_lpart[p1]);
    const float4 o0 = ((const float4*)&g_Opart[p0 * CDIM])[c4];
    const float4 o1 = ((const float4*)&g_Opart[p1 * CDIM])[c4];
    const float4 xv = ((const float4*)&x[((size_t)b * NSEQ + r) * CDIM])[c4];
    const float gg = gamma[0];
    float4 o;
    o.x = gg * (w0 * o0.x + w1 * o1.x) * inv + xv.x;
    o.y = gg * (w0 * o0.y + w1 * o1.y) * inv + xv.y;
    o.z = gg * (w0 * o0.z + w1 * o1.z) * inv + xv.z;
    o.w = gg * (w0 * o0.w + w1 * o1.w) * inv + xv.w;
    ((float4*)&out[((size_t)b * NSEQ + r) * CDIM])[c4] = o;
}

extern "C" void kernel_launch(void* const* d_in, const int* in_sizes, int n_in,
                              void* d_out, int out_size)
{
    const float* x     = (const float*)d_in[0];
    const float* gamma = (const float*)d_in[1];
    float* out = (float*)d_out;
    (void)in_sizes; (void)n_in; (void)out_size;

    cudaFuncSetAttribute(attn_main, cudaFuncAttributeMaxDynamicSharedMemorySize, SMEM_BYTES);
    attn_main<<<dim3(NSEQ / MT, 2, 2), 128, SMEM_BYTES>>>(x);
    merge_kernel<<<512, 256>>>(x, gamma, out);
}

// round 8
// speedup vs baseline: 3.7170x; 1.1403x over previous
#include <cuda_runtime.h>
#include <cuda_fp16.h>
#include <math.h>
#include <stdint.h>

#define NSEQ  4096
#define CDIM  64
#define MT    64
#define KB    128
#define KHALF 2048
#define NBLK  (KHALF / KB)

// scratch (allocation-free rule -> __device__ globals)
__device__ __half g_xh[2 * NSEQ * CDIM];
__device__ __half g_xl[2 * NSEQ * CDIM];
__device__ float g_Opart[2 * 2 * NSEQ * CDIM];
__device__ float g_lpart[2 * 2 * NSEQ];
__device__ float g_mpart[2 * 2 * NSEQ];

// smem layout (bytes): Q hi/lo 64x128B each; X double-buffered hi/lo 128x128B each
#define QH_OFF 0u
#define QL_OFF 8192u
#define XB_OFF 16384u              // buf b at XB_OFF + b*32768 (hi), +16384 (lo)
#define SMEM_BYTES 81920u

__device__ __forceinline__ uint32_t cvta_smem(const void* p) {
    uint32_t a;
    asm("{ .reg .u64 t; cvta.to.shared.u64 t, %1; cvt.u32.u64 %0, t; }" : "=r"(a) : "l"(p));
    return a;
}
__device__ __forceinline__ void ldsm4(uint32_t addr, uint32_t* r) {
    asm volatile("ldmatrix.sync.aligned.m8n8.x4.shared.b16 {%0,%1,%2,%3}, [%4];"
                 : "=r"(r[0]), "=r"(r[1]), "=r"(r[2]), "=r"(r[3]) : "r"(addr));
}
__device__ __forceinline__ void ldsm4t(uint32_t addr, uint32_t* r) {
    asm volatile("ldmatrix.sync.aligned.m8n8.x4.trans.shared.b16 {%0,%1,%2,%3}, [%4];"
                 : "=r"(r[0]), "=r"(r[1]), "=r"(r[2]), "=r"(r[3]) : "r"(addr));
}
__device__ __forceinline__ void mma16816(float* c, const uint32_t* a, const uint32_t* b) {
    asm volatile("mma.sync.aligned.m16n8k16.row.col.f32.f16.f16.f32 "
                 "{%0,%1,%2,%3}, {%4,%5,%6,%7}, {%8,%9}, {%0,%1,%2,%3};"
                 : "+f"(c[0]), "+f"(c[1]), "+f"(c[2]), "+f"(c[3])
                 : "r"(a[0]), "r"(a[1]), "r"(a[2]), "r"(a[3]), "r"(b[0]), "r"(b[1]));
}
__device__ __forceinline__ void cp16(uint32_t dst, const void* src) {
    asm volatile("cp.async.cg.shared.global [%0], [%1], 16;" :: "r"(dst), "l"(src));
}
#define CP_COMMIT()  asm volatile("cp.async.commit_group;" ::: "memory")
#define CP_WAIT(n)   asm volatile("cp.async.wait_group %0;" :: "n"(n) : "memory")

// XOR-swizzled byte offset inside a 128B-row tile
__device__ __forceinline__ uint32_t swz(uint32_t tb, int row, int cb) {
    return tb + row * 128 + (((((unsigned)cb >> 4) ^ (row & 7)) << 4) | (cb & 15));
}

// ---- pre-pass: split fp32 x into fp16 hi + lo ----
__global__ __launch_bounds__(256) void split_kernel(const float* __restrict__ x)
{
    const int i = blockIdx.x * 256 + threadIdx.x;   // 131072 float4s
    float4 v = ((const float4*)x)[i];
    __half h0 = __float2half_rn(v.x), h1 = __float2half_rn(v.y);
    __half h2 = __float2half_rn(v.z), h3 = __float2half_rn(v.w);
    __half2 H0 = __halves2half2(h0, h1), H1 = __halves2half2(h2, h3);
    __half2 L0 = __floats2half2_rn(v.x - __half2float(h0), v.y - __half2float(h1));
    __half2 L1 = __floats2half2_rn(v.z - __half2float(h2), v.w - __half2float(h3));
    ((uint2*)g_xh)[i] = make_uint2(*(uint32_t*)&H0, *(uint32_t*)&H1);
    ((uint2*)g_xl)[i] = make_uint2(*(uint32_t*)&L0, *(uint32_t*)&L1);
}

__global__ __launch_bounds__(128, 2) void attn_main()
{
    extern __shared__ char sm[];
    const uint32_t sb = cvta_smem(sm);
    const int tid = threadIdx.x, lane = tid & 31, w = tid >> 5;
    const int qb = blockIdx.x * MT, b = blockIdx.y, kh = blockIdx.z;
    const __half* xh = g_xh + (size_t)b * NSEQ * CDIM;
    const __half* xl = g_xl + (size_t)b * NSEQ * CDIM;

    // prologue: Q hi/lo + X block 0 via cp.async (one group)
    {
        const int row = tid >> 1, h = tid & 1;
        #pragma unroll
        for (int i = 0; i < 4; ++i) {
            const int cb = h * 64 + i * 16;     // byte col within 128B row
            cp16(swz(sb + QH_OFF, row, cb), xh + (size_t)(qb + row) * CDIM + h * 32 + i * 8);
            cp16(swz(sb + QL_OFF, row, cb), xl + (size_t)(qb + row) * CDIM + h * 32 + i * 8);
        }
        const size_t xrow = (size_t)(kh * KHALF + tid) * CDIM;
        #pragma unroll
        for (int i = 0; i < 8; ++i) {
            cp16(swz(sb + XB_OFF, tid, i * 16), xh + xrow + i * 8);
            cp16(swz(sb + XB_OFF + 16384u, tid, i * 16), xl + xrow + i * 8);
        }
        CP_COMMIT();
    }

    const int r0 = w * 16;
    const int g = lane >> 3, lr = lane & 7;
    float m0 = -1e30f, m1 = -1e30f, l0 = 0.f, l1 = 0.f;
    float O[8][4];
    #pragma unroll
    for (int jc = 0; jc < 8; ++jc)
        #pragma unroll
        for (int q = 0; q < 4; ++q) O[jc][q] = 0.f;

    for (int blk = 0; blk < NBLK; ++blk) {
        const uint32_t XH = sb + XB_OFF + (blk & 1) * 32768u;
        const uint32_t XL = XH + 16384u;

        // issue next block's loads into the other buffer (prev compute synced)
        if (blk + 1 < NBLK) {
            const uint32_t NH = sb + XB_OFF + ((blk + 1) & 1) * 32768u;
            const size_t xrow = (size_t)(kh * KHALF + (blk + 1) * KB + tid) * CDIM;
            #pragma unroll
            for (int i = 0; i < 8; ++i) {
                cp16(swz(NH, tid, i * 16), xh + xrow + i * 8);
                cp16(swz(NH + 16384u, tid, i * 16), xl + xrow + i * 8);
            }
            CP_COMMIT();
            CP_WAIT(1);
        } else {
            CP_WAIT(0);
        }
        __syncthreads();

        // ---- GEMM1: S[16 rows][128 keys] per warp (3-term split) ----
        uint32_t aH[4][4], aL[4][4];
        {
            const int arow = r0 + (g & 1) * 8 + lr;
            const int acb  = (g >> 1) * 16;
            #pragma unroll
            for (int k = 0; k < 4; ++k) {
                ldsm4(swz(sb + QH_OFF, arow, k * 32 + acb), aH[k]);
                ldsm4(swz(sb + QL_OFF, arow, k * 32 + acb), aL[k]);
            }
        }
        float S[16][4];
        #pragma unroll
        for (int j = 0; j < 16; ++j)
            #pragma unroll
            for (int q = 0; q < 4; ++q) S[j][q] = 0.f;

        #pragma unroll
        for (int j = 0; j < 16; ++j) {
            const int krow = j * 8 + lr;
            uint32_t t0[4], t1[4], u0[4], u1[4];
            ldsm4(swz(XH, krow, g * 16), t0);
            ldsm4(swz(XH, krow, 64 + g * 16), t1);
            ldsm4(swz(XL, krow, g * 16), u0);
            ldsm4(swz(XL, krow, 64 + g * 16), u1);
            uint32_t bh[4][2] = {{t0[0],t0[1]},{t0[2],t0[3]},{t1[0],t1[1]},{t1[2],t1[3]}};
            uint32_t bl[4][2] = {{u0[0],u0[1]},{u0[2],u0[3]},{u1[0],u1[1]},{u1[2],u1[3]}};
            #pragma unroll
            for (int k = 0; k < 4; ++k) {
                mma16816(S[j], aH[k], bh[k]);
                mma16816(S[j], aH[k], bl[k]);
                mma16816(S[j], aL[k], bh[k]);
            }
        }

        // ---- online softmax ----
        float mx0 = -1e30f, mx1 = -1e30f;
        #pragma unroll
        for (int j = 0; j < 16; ++j) {
            mx0 = fmaxf(mx0, fmaxf(S[j][0], S[j][1]));
            mx1 = fmaxf(mx1, fmaxf(S[j][2], S[j][3]));
        }
        mx0 = fmaxf(mx0, __shfl_xor_sync(0xffffffffu, mx0, 1));
        mx0 = fmaxf(mx0, __shfl_xor_sync(0xffffffffu, mx0, 2));
        mx1 = fmaxf(mx1, __shfl_xor_sync(0xffffffffu, mx1, 1));
        mx1 = fmaxf(mx1, __shfl_xor_sync(0xffffffffu, mx1, 2));
        const float mn0 = fmaxf(m0, mx0), mn1 = fmaxf(m1, mx1);
        const float cr0 = __expf(m0 - mn0), cr1 = __expf(m1 - mn1);
        m0 = mn0; m1 = mn1;

        float s0 = 0.f, s1 = 0.f;
        uint32_t Ph[16][2];
        #pragma unroll
        for (int j = 0; j < 16; ++j) {
            float p0 = __expf(S[j][0] - mn0), p1 = __expf(S[j][1] - mn0);
            float p2 = __expf(S[j][2] - mn1), p3 = __expf(S[j][3] - mn1);
            s0 += p0 + p1; s1 += p2 + p3;
            __half2 H0 = __floats2half2_rn(p0, p1), H1 = __floats2half2_rn(p2, p3);
            Ph[j][0] = *(uint32_t*)&H0; Ph[j][1] = *(uint32_t*)&H1;
        }
        s0 += __shfl_xor_sync(0xffffffffu, s0, 1);
        s0 += __shfl_xor_sync(0xffffffffu, s0, 2);
        s1 += __shfl_xor_sync(0xffffffffu, s1, 1);
        s1 += __shfl_xor_sync(0xffffffffu, s1, 2);
        l0 = l0 * cr0 + s0; l1 = l1 * cr1 + s1;
        #pragma unroll
        for (int jc = 0; jc < 8; ++jc) {
            O[jc][0] *= cr0; O[jc][1] *= cr0; O[jc][2] *= cr1; O[jc][3] *= cr1;
        }

        // ---- GEMM2: O[16 rows][64 ch] += Ph[16][128] * Vh[128][64] ----
        #pragma unroll
        for (int jc = 0; jc < 8; ++jc) {
            uint32_t vh[8][2];
            #pragma unroll
            for (int kp = 0; kp < 4; ++kp) {
                uint32_t t[4];
                const int key = kp * 32 + g * 8 + lr;
                ldsm4t(swz(XH, key, jc * 16), t);
                vh[2*kp][0] = t[0]; vh[2*kp][1] = t[1];
                vh[2*kp+1][0] = t[2]; vh[2*kp+1][1] = t[3];
            }
            #pragma unroll
            for (int kk = 0; kk < 8; ++kk) {
                uint32_t Ah[4] = {Ph[2*kk][0], Ph[2*kk][1], Ph[2*kk+1][0], Ph[2*kk+1][1]};
                mma16816(O[jc], Ah, vh[kk]);
            }
        }
        __syncthreads();   // all warps done with this buffer before it is overwritten
    }

    // ---- write per-half partials ----
    const int ra = qb + r0 + (lane >> 2);
    const size_t pb = (size_t)(b * 2 + kh) * NSEQ;
    if ((lane & 3) == 0) {
        g_mpart[pb + ra] = m0;     g_lpart[pb + ra] = l0;
        g_mpart[pb + ra + 8] = m1; g_lpart[pb + ra + 8] = l1;
    }
    #pragma unroll
    for (int jc = 0; jc < 8; ++jc) {
        const int ch = jc * 8 + 2 * (lane & 3);
        *(float2*)&g_Opart[(pb + ra) * CDIM + ch]     = make_float2(O[jc][0], O[jc][1]);
        *(float2*)&g_Opart[(pb + ra + 8) * CDIM + ch] = make_float2(O[jc][2], O[jc][3]);
    }
}

__global__ __launch_bounds__(256) void merge_kernel(const float* __restrict__ x,
                                                    const float* __restrict__ gamma,
                                                    float* __restrict__ out)
{
    const int i = blockIdx.x * 256 + threadIdx.x;      // 131072 float4s total
    const int c4 = i & 15;
    const int r  = (i >> 4) & (NSEQ - 1);
    const int b  = i >> 16;
    const size_t p0 = (size_t)(b * 2) * NSEQ + r, p1 = p0 + NSEQ;
    const float M  = fmaxf(g_mpart[p0], g_mpart[p1]);
    const float w0 = __expf(g_mpart[p0] - M), w1 = __expf(g_mpart[p1] - M);
    const float inv = 1.0f / (w0 * g_lpart[p0] + w1 * g_lpart[p1]);
    const float4 o0 = ((const float4*)&g_Opart[p0 * CDIM])[c4];
    const float4 o1 = ((const float4*)&g_Opart[p1 * CDIM])[c4];
    const float4 xv = ((const float4*)&x[((size_t)b * NSEQ + r) * CDIM])[c4];
    const float gg = gamma[0];
    float4 o;
    o.x = gg * (w0 * o0.x + w1 * o1.x) * inv + xv.x;
    o.y = gg * (w0 * o0.y + w1 * o1.y) * inv + xv.y;
    o.z = gg * (w0 * o0.z + w1 * o1.z) * inv + xv.z;
    o.w = gg * (w0 * o0.w + w1 * o1.w) * inv + xv.w;
    ((float4*)&out[((size_t)b * NSEQ + r) * CDIM])[c4] = o;
}

extern "C" void kernel_launch(void* const* d_in, const int* in_sizes, int n_in,
                              void* d_out, int out_size)
{
    const float* x     = (const float*)d_in[0];
    const float* gamma = (const float*)d_in[1];
    float* out = (float*)d_out;
    (void)in_sizes; (void)n_in; (void)out_size;

    cudaFuncSetAttribute(attn_main, cudaFuncAttributeMaxDynamicSharedMemorySize, SMEM_BYTES);
    split_kernel<<<512, 256>>>(x);
    attn_main<<<dim3(NSEQ / MT, 2, 2), 128, SMEM_BYTES>>>();
    merge_kernel<<<512, 256>>>(x, gamma, out);
}